// round 2
// baseline (speedup 1.0000x reference)
#include <cuda_runtime.h>
#include <cstdint>

// Problem dims (fixed by the dataset)
#define BATCH 256
#define SEQ   197
#define SN    196      // SEQ-1
#define DIM   768
#define GRID  14
#define MQK   (BATCH*SEQ)    // 50432
#define MH    (BATCH*SN)     // 50176
#define MV    (BATCH*64)     // 16384 (only 8x8 grid cells [6,13]^2 reachable)
#define H60   60
#define K2    1536

// -------- scratch (__device__ globals; no allocation allowed) --------
__device__ float g_q [(size_t)MQK * DIM];
__device__ float g_k [(size_t)MQK * DIM];
__device__ float g_vs[(size_t)MV  * DIM];
__device__ float g_h1[(size_t)MH  * H60];
__device__ float g_sample[(size_t)MH * 2];
__device__ float g_coords[(size_t)MH * 2];

// ============================================================
// 128x128x8 fp32 SGEMM tile, 256 threads, 8x8 microtile.
// Y[r,e] = sum_d A[r,d]*W[e,d] + bias[e]
// Used for Q and K (blockIdx.z selects which).
// ============================================================
__global__ __launch_bounds__(256) void k_gemm_qk(
    const float* __restrict__ X,
    const float* __restrict__ Wq, const float* __restrict__ bq,
    const float* __restrict__ Wk, const float* __restrict__ bk)
{
    const float* W    = blockIdx.z ? Wk : Wq;
    const float* bias = blockIdx.z ? bk : bq;
    float*       Y    = blockIdx.z ? g_k : g_q;

    __shared__ __align__(16) float As[8][132];
    __shared__ __align__(16) float Bs[8][132];

    const int tid = threadIdx.x;
    const int lr  = tid >> 1;          // 0..127
    const int lc  = (tid & 1) * 4;     // 0 or 4
    const int row0 = blockIdx.x * 128;
    const int col0 = blockIdx.y * 128;

    const float* Ap = X + (size_t)(row0 + lr) * DIM + lc;
    const float* Bp = W + (size_t)(col0 + lr) * DIM + lc;

    const int ty = tid >> 4;           // 0..15
    const int tx = tid & 15;           // 0..15

    float acc[8][8];
    #pragma unroll
    for (int i = 0; i < 8; i++)
        #pragma unroll
        for (int j = 0; j < 8; j++) acc[i][j] = 0.f;

    for (int k0 = 0; k0 < DIM; k0 += 8) {
        float4 a = *reinterpret_cast<const float4*>(Ap + k0);
        float4 b = *reinterpret_cast<const float4*>(Bp + k0);
        As[lc+0][lr] = a.x; As[lc+1][lr] = a.y; As[lc+2][lr] = a.z; As[lc+3][lr] = a.w;
        Bs[lc+0][lr] = b.x; Bs[lc+1][lr] = b.y; Bs[lc+2][lr] = b.z; Bs[lc+3][lr] = b.w;
        __syncthreads();
        #pragma unroll
        for (int kk = 0; kk < 8; kk++) {
            float4 a0 = *reinterpret_cast<const float4*>(&As[kk][ty*4]);
            float4 a1 = *reinterpret_cast<const float4*>(&As[kk][64 + ty*4]);
            float4 b0 = *reinterpret_cast<const float4*>(&Bs[kk][tx*4]);
            float4 b1 = *reinterpret_cast<const float4*>(&Bs[kk][64 + tx*4]);
            float av[8] = {a0.x,a0.y,a0.z,a0.w,a1.x,a1.y,a1.z,a1.w};
            float bv[8] = {b0.x,b0.y,b0.z,b0.w,b1.x,b1.y,b1.z,b1.w};
            #pragma unroll
            for (int i = 0; i < 8; i++)
                #pragma unroll
                for (int j = 0; j < 8; j++)
                    acc[i][j] = fmaf(av[i], bv[j], acc[i][j]);
        }
        __syncthreads();
    }

    // bias into registers once
    float bias_lo[4], bias_hi[4];
    #pragma unroll
    for (int j = 0; j < 4; j++) {
        bias_lo[j] = bias[col0 + tx*4 + j];
        bias_hi[j] = bias[col0 + 64 + tx*4 + j];
    }

    #pragma unroll
    for (int i = 0; i < 8; i++) {
        int r = row0 + ((i < 4) ? (ty*4 + i) : (64 + ty*4 + i - 4));
        float* yr = Y + (size_t)r * DIM + col0;
        float4 o0, o1;
        o0.x = acc[i][0] + bias_lo[0]; o0.y = acc[i][1] + bias_lo[1];
        o0.z = acc[i][2] + bias_lo[2]; o0.w = acc[i][3] + bias_lo[3];
        o1.x = acc[i][4] + bias_hi[0]; o1.y = acc[i][5] + bias_hi[1];
        o1.z = acc[i][6] + bias_hi[2]; o1.w = acc[i][7] + bias_hi[3];
        *reinterpret_cast<float4*>(yr + tx*4)      = o0;
        *reinterpret_cast<float4*>(yr + 64 + tx*4) = o1;
    }
}

// ============================================================
// V projection restricted to the 64 reachable tokens per batch.
// Row r -> (b = r>>6, j = r&63), token = 1 + (6+j/8)*14 + (6+j%8)
// ============================================================
__global__ __launch_bounds__(256) void k_gemm_v(
    const float* __restrict__ X,
    const float* __restrict__ Wv, const float* __restrict__ bv)
{
    __shared__ __align__(16) float As[8][132];
    __shared__ __align__(16) float Bs[8][132];

    const int tid = threadIdx.x;
    const int lr  = tid >> 1;
    const int lc  = (tid & 1) * 4;
    const int row0 = blockIdx.x * 128;
    const int col0 = blockIdx.y * 128;

    const int r_g = row0 + lr;
    const int bb  = r_g >> 6;
    const int jj  = r_g & 63;
    const int token = 1 + (6 + (jj >> 3)) * GRID + (6 + (jj & 7));
    const float* Ap = X + (size_t)(bb * SEQ + token) * DIM + lc;
    const float* Bp = Wv + (size_t)(col0 + lr) * DIM + lc;

    const int ty = tid >> 4;
    const int tx = tid & 15;

    float acc[8][8];
    #pragma unroll
    for (int i = 0; i < 8; i++)
        #pragma unroll
        for (int j = 0; j < 8; j++) acc[i][j] = 0.f;

    for (int k0 = 0; k0 < DIM; k0 += 8) {
        float4 a = *reinterpret_cast<const float4*>(Ap + k0);
        float4 b = *reinterpret_cast<const float4*>(Bp + k0);
        As[lc+0][lr] = a.x; As[lc+1][lr] = a.y; As[lc+2][lr] = a.z; As[lc+3][lr] = a.w;
        Bs[lc+0][lr] = b.x; Bs[lc+1][lr] = b.y; Bs[lc+2][lr] = b.z; Bs[lc+3][lr] = b.w;
        __syncthreads();
        #pragma unroll
        for (int kk = 0; kk < 8; kk++) {
            float4 a0 = *reinterpret_cast<const float4*>(&As[kk][ty*4]);
            float4 a1 = *reinterpret_cast<const float4*>(&As[kk][64 + ty*4]);
            float4 b0 = *reinterpret_cast<const float4*>(&Bs[kk][tx*4]);
            float4 b1 = *reinterpret_cast<const float4*>(&Bs[kk][64 + tx*4]);
            float av[8] = {a0.x,a0.y,a0.z,a0.w,a1.x,a1.y,a1.z,a1.w};
            float bv8[8] = {b0.x,b0.y,b0.z,b0.w,b1.x,b1.y,b1.z,b1.w};
            #pragma unroll
            for (int i = 0; i < 8; i++)
                #pragma unroll
                for (int j = 0; j < 8; j++)
                    acc[i][j] = fmaf(av[i], bv8[j], acc[i][j]);
        }
        __syncthreads();
    }

    float bias_lo[4], bias_hi[4];
    #pragma unroll
    for (int j = 0; j < 4; j++) {
        bias_lo[j] = bv[col0 + tx*4 + j];
        bias_hi[j] = bv[col0 + 64 + tx*4 + j];
    }

    #pragma unroll
    for (int i = 0; i < 8; i++) {
        int r = row0 + ((i < 4) ? (ty*4 + i) : (64 + ty*4 + i - 4));
        float* yr = g_vs + (size_t)r * DIM + col0;
        float4 o0, o1;
        o0.x = acc[i][0] + bias_lo[0]; o0.y = acc[i][1] + bias_lo[1];
        o0.z = acc[i][2] + bias_lo[2]; o0.w = acc[i][3] + bias_lo[3];
        o1.x = acc[i][4] + bias_hi[0]; o1.y = acc[i][5] + bias_hi[1];
        o1.z = acc[i][6] + bias_hi[2]; o1.w = acc[i][7] + bias_hi[3];
        *reinterpret_cast<float4*>(yr + tx*4)      = o0;
        *reinterpret_cast<float4*>(yr + 64 + tx*4) = o1;
    }
}

// ============================================================
// MLP layer 1: h1 = relu(concat(q_nc,k_nc) @ W1^T + b1)
// M=50176, K=1536, N=60 (tile N=64, guard). A is virtual:
// row r=(b,t): d<768 -> q[b,t+1,d], else k[b,t+1,d-768]
// ============================================================
__global__ __launch_bounds__(256) void k_gemm_h1(
    const float* __restrict__ W1, const float* __restrict__ b1)
{
    __shared__ __align__(16) float As[8][132];
    __shared__ __align__(16) float Bs[8][68];

    const int tid = threadIdx.x;
    const int lr  = tid >> 1;
    const int lc  = (tid & 1) * 4;
    const int row0 = blockIdx.x * 128;

    const int r_g = row0 + lr;
    const int bb  = r_g / SN;
    const int tt  = r_g - bb * SN;
    const size_t abase = (size_t)(bb * SEQ + tt + 1) * DIM + lc;

    // B loader: tid<128, e = tid>>1 in [0,64), col4 = (tid&1)*4
    const int blr = tid >> 1;
    const int blc = (tid & 1) * 4;

    const int ty = tid >> 4;
    const int tx = tid & 15;

    float acc[8][4];
    #pragma unroll
    for (int i = 0; i < 8; i++)
        #pragma unroll
        for (int j = 0; j < 4; j++) acc[i][j] = 0.f;

    for (int k0 = 0; k0 < K2; k0 += 8) {
        int d = k0 + lc;
        const float* ap = (d < DIM) ? (g_q + abase + (size_t)k0)
                                    : (g_k + abase + (size_t)(k0 - DIM));
        float4 a = *reinterpret_cast<const float4*>(ap);
        As[lc+0][lr] = a.x; As[lc+1][lr] = a.y; As[lc+2][lr] = a.z; As[lc+3][lr] = a.w;
        if (tid < 128) {
            float4 b = make_float4(0.f, 0.f, 0.f, 0.f);
            if (blr < H60)
                b = *reinterpret_cast<const float4*>(W1 + (size_t)blr * K2 + k0 + blc);
            Bs[blc+0][blr] = b.x; Bs[blc+1][blr] = b.y; Bs[blc+2][blr] = b.z; Bs[blc+3][blr] = b.w;
        }
        __syncthreads();
        #pragma unroll
        for (int kk = 0; kk < 8; kk++) {
            float4 a0 = *reinterpret_cast<const float4*>(&As[kk][ty*4]);
            float4 a1 = *reinterpret_cast<const float4*>(&As[kk][64 + ty*4]);
            float4 b0 = *reinterpret_cast<const float4*>(&Bs[kk][tx*4]);
            float av[8] = {a0.x,a0.y,a0.z,a0.w,a1.x,a1.y,a1.z,a1.w};
            float bv4[4] = {b0.x,b0.y,b0.z,b0.w};
            #pragma unroll
            for (int i = 0; i < 8; i++)
                #pragma unroll
                for (int j = 0; j < 4; j++)
                    acc[i][j] = fmaf(av[i], bv4[j], acc[i][j]);
        }
        __syncthreads();
    }

    #pragma unroll
    for (int i = 0; i < 8; i++) {
        int r = row0 + ((i < 4) ? (ty*4 + i) : (64 + ty*4 + i - 4));
        #pragma unroll
        for (int j = 0; j < 4; j++) {
            int c = tx*4 + j;
            if (c < H60)
                g_h1[(size_t)r * H60 + c] = fmaxf(acc[i][j] + b1[c], 0.f);
        }
    }
}

// ============================================================
// MLP layers 2+3: h2 = relu(h1@W2^T+b2); sample = sigmoid(h2@W3^T+b3)
// 4 tokens per 256-thread block; W2 cached in smem.
// ============================================================
__global__ __launch_bounds__(256) void k_mlp23(
    const float* __restrict__ W2, const float* __restrict__ b2,
    const float* __restrict__ W3, const float* __restrict__ b3)
{
    __shared__ float W2s[3600];
    __shared__ float W3s[120];
    __shared__ float b2s[60], b3s[2];
    __shared__ float h1s[4][60];
    __shared__ float h2s[4][60];

    const int tid = threadIdx.x;
    for (int i = tid; i < 3600; i += 256) W2s[i] = W2[i];
    if (tid < 120) W3s[tid] = W3[tid];
    if (tid < 60)  b2s[tid] = b2[tid];
    if (tid < 2)   b3s[tid] = b3[tid];

    const int tl = tid >> 6;      // 0..3 token within block
    const int f  = tid & 63;
    const int r  = blockIdx.x * 4 + tl;
    if (f < H60) h1s[tl][f] = g_h1[(size_t)r * H60 + f];
    __syncthreads();

    if (f < H60) {
        float s = b2s[f];
        #pragma unroll 6
        for (int g = 0; g < H60; g++) s = fmaf(W2s[f*60 + g], h1s[tl][g], s);
        h2s[tl][f] = fmaxf(s, 0.f);
    }
    __syncthreads();

    if (tid < 8) {
        int t2 = tid >> 1, c = tid & 1;
        float s = b3s[c];
        #pragma unroll 6
        for (int g = 0; g < H60; g++) s = fmaf(W3s[c*60 + g], h2s[t2][g], s);
        int rr = blockIdx.x * 4 + t2;
        g_sample[(size_t)rr * 2 + c] = 1.f / (1.f + expf(-s));
    }
}

// ============================================================
// Grid coordinate shuffle + unnormalize.
// arr[t] = t<196 ? sample[t][0] : sample[t-196][1]; gx=arr[2p], gy=arr[2p+1]
// ============================================================
__global__ void k_coords()
{
    const int id = blockIdx.x * 256 + threadIdx.x;   // grid 196*256 = exactly 50176
    const int b = id / SN;
    const int p = id - b * SN;
    const int q1 = 2 * p;
    const int q2 = 2 * p + 1;
    float gx = (q1 < SN) ? g_sample[(size_t)(b*SN + q1)*2 + 0]
                         : g_sample[(size_t)(b*SN + q1 - SN)*2 + 1];
    float gy = (q2 < SN) ? g_sample[(size_t)(b*SN + q2)*2 + 0]
                         : g_sample[(size_t)(b*SN + q2 - SN)*2 + 1];
    g_coords[(size_t)id*2 + 0] = ((gx + 1.f) * (float)GRID - 1.f) * 0.5f;
    g_coords[(size_t)id*2 + 1] = ((gy + 1.f) * (float)GRID - 1.f) * 0.5f;
}

// ============================================================
// Epilogue: per (b,s) block — bilinear gather sk/sv, score = dot(sk,q),
// out = sigmoid(TEMP*score) * sv.  s=0 is the CLS row (sk=sv=1).
// ============================================================
__global__ __launch_bounds__(256) void k_epilogue(float* __restrict__ out)
{
    const int bs = blockIdx.x;              // 0..50431
    const int b  = bs / SEQ;
    const int s  = bs - b * SEQ;
    const int tid = threadIdx.x;
    __shared__ float red[256];
    __shared__ float sigsh;

    const size_t qbase = (size_t)bs * DIM;

    float  w[4];
    size_t rowk[4], rowv[4];
    bool   vk[4], vv[4];

    if (s > 0) {
        const int p = s - 1;
        const float ix = g_coords[(size_t)(b*SN + p)*2 + 0];
        const float iy = g_coords[(size_t)(b*SN + p)*2 + 1];
        const float ix0f = floorf(ix), iy0f = floorf(iy);
        const float wx1 = ix - ix0f, wx0 = 1.f - wx1;
        const float wy1 = iy - iy0f, wy0 = 1.f - wy1;
        const int x0 = (int)ix0f, y0 = (int)iy0f;
        const int xs[4] = {x0, x0+1, x0,   x0+1};
        const int ys[4] = {y0, y0,   y0+1, y0+1};
        const float ws[4] = {wy0*wx0, wy0*wx1, wy1*wx0, wy1*wx1};
        #pragma unroll
        for (int c = 0; c < 4; c++) {
            const int x = xs[c], y = ys[c];
            const bool v = (x >= 0) && (x <= GRID-1) && (y >= 0) && (y <= GRID-1);
            vk[c] = v;
            w[c]  = ws[c];
            const int tok = 1 + y * GRID + x;
            rowk[c] = v ? (size_t)(b * SEQ + tok) * DIM : 0;
            const bool v2 = v && (x >= 6) && (y >= 6);   // reachable set; x,y<=13 already
            vv[c]   = v2;
            rowv[c] = v2 ? (size_t)(b * 64 + (y-6)*8 + (x-6)) * DIM : 0;
        }
    }

    float part = 0.f;
    float svreg[3];
    #pragma unroll
    for (int it = 0; it < 3; it++) {
        const int d = tid + it * 256;
        float skd, svd;
        if (s == 0) {
            skd = 1.f; svd = 1.f;
        } else {
            skd = 0.f; svd = 0.f;
            #pragma unroll
            for (int c = 0; c < 4; c++) {
                if (vk[c]) skd = fmaf(w[c], g_k[rowk[c] + d], skd);
                if (vv[c]) svd = fmaf(w[c], g_vs[rowv[c] + d], svd);
            }
        }
        svreg[it] = svd;
        part = fmaf(skd, g_q[qbase + d], part);
    }

    red[tid] = part;
    __syncthreads();
    #pragma unroll
    for (int off = 128; off > 0; off >>= 1) {
        if (tid < off) red[tid] += red[tid + off];
        __syncthreads();
    }
    if (tid == 0) sigsh = 1.f / (1.f + expf(-0.01f * red[0]));
    __syncthreads();
    const float sg = sigsh;
    #pragma unroll
    for (int it = 0; it < 3; it++)
        out[qbase + tid + it * 256] = sg * svreg[it];
}

// ============================================================
extern "C" void kernel_launch(void* const* d_in, const int* in_sizes, int n_in,
                              void* d_out, int out_size)
{
    const float* x   = (const float*)d_in[0];
    // d_in[1] = mask (unused by reference result)
    const float* Wq  = (const float*)d_in[2];
    const float* bq  = (const float*)d_in[3];
    const float* Wk  = (const float*)d_in[4];
    const float* bk  = (const float*)d_in[5];
    const float* Wv  = (const float*)d_in[6];
    const float* bv  = (const float*)d_in[7];
    const float* W1  = (const float*)d_in[8];
    const float* b1  = (const float*)d_in[9];
    const float* W2  = (const float*)d_in[10];
    const float* b2  = (const float*)d_in[11];
    const float* W3  = (const float*)d_in[12];
    const float* b3  = (const float*)d_in[13];
    float* out = (float*)d_out;

    // Q,K full projections: M=50432 (394 tiles), N=768 (6 tiles), z selects Q/K
    k_gemm_qk<<<dim3(394, 6, 2), 256>>>(x, Wq, bq, Wk, bk);
    // V projection on the 64 reachable tokens/batch: M=16384 (128 tiles)
    k_gemm_v<<<dim3(128, 6), 256>>>(x, Wv, bv);
    // MLP layer 1 (reads g_q, g_k): M=50176 (392 tiles)
    k_gemm_h1<<<dim3(392, 1), 256>>>(W1, b1);
    // MLP layers 2+3 -> sample
    k_mlp23<<<12544, 256>>>(W2, b2, W3, b3);
    // grid coordinate shuffle
    k_coords<<<196, 256>>>();
    // bilinear sample + scores + output
    k_epilogue<<<MQK, 256>>>(out);
}

// round 3
// speedup vs baseline: 2.2667x; 2.2667x over previous
#include <cuda_runtime.h>
#include <cstdint>

// Problem dims (fixed by the dataset)
#define BATCH 256
#define SEQ   197
#define SN    196      // SEQ-1
#define DIM   768
#define GRID  14
#define MQK   (BATCH*SEQ)    // 50432
#define MH    (BATCH*SN)     // 50176
#define MV    (BATCH*64)     // 16384 (only 8x8 grid cells [6,13]^2 reachable)
#define H60   60
#define K2    1536

// -------- scratch (__device__ globals; no allocation allowed) --------
__device__ float g_q [(size_t)MQK * DIM];
__device__ float g_k [(size_t)MQK * DIM];
__device__ float g_vs[(size_t)MV  * DIM];
__device__ float g_h1[(size_t)MH  * H60];
__device__ float g_sample[(size_t)MH * 2];
__device__ float g_coords[(size_t)MH * 2];

// ---------------- tf32 helpers ----------------
__device__ __forceinline__ uint32_t f2tf32(float f) {
    uint32_t u;
    asm("cvt.rna.tf32.f32 %0, %1;" : "=r"(u) : "f"(f));
    return u;
}

__device__ __forceinline__ void mma_tf32(float (&d)[4], const uint32_t (&a)[4], const uint32_t (&b)[2]) {
    asm volatile(
        "mma.sync.aligned.m16n8k8.row.col.f32.tf32.tf32.f32 "
        "{%0,%1,%2,%3}, {%4,%5,%6,%7}, {%8,%9}, {%0,%1,%2,%3};\n"
        : "+f"(d[0]), "+f"(d[1]), "+f"(d[2]), "+f"(d[3])
        : "r"(a[0]), "r"(a[1]), "r"(a[2]), "r"(a[3]), "r"(b[0]), "r"(b[1]));
}

// ============================================================
// TF32 tensor-core GEMM: Y[r,e] = sum_d A[r,d]*W[e,d] + bias[e]
// Block 128x128, K-step 32. 8 warps = 2(M) x 4(N); warp tile 64x32.
// Q and K share the kernel via blockIdx.z.
// ============================================================
__global__ __launch_bounds__(256) void k_gemm_qk_t(
    const float* __restrict__ X,
    const float* __restrict__ Wq, const float* __restrict__ bq,
    const float* __restrict__ Wk, const float* __restrict__ bk)
{
    const float* W    = blockIdx.z ? Wk : Wq;
    const float* bias = blockIdx.z ? bk : bq;
    float*       Y    = blockIdx.z ? g_k : g_q;

    __shared__ __align__(16) uint32_t As[128][36];
    __shared__ __align__(16) uint32_t Bs[128][36];

    const int tid  = threadIdx.x;
    const int lane = tid & 31;
    const int wid  = tid >> 5;
    const int warpM = wid & 1;
    const int warpN = wid >> 1;

    const int row0 = blockIdx.x * 128;
    const int col0 = blockIdx.y * 128;

    const int ldr = tid >> 1;
    const int ldc = (tid & 1) * 16;

    const float* Ap = X + (size_t)(row0 + ldr) * DIM + ldc;
    const float* Bp = W + (size_t)(col0 + ldr) * DIM + ldc;

    float acc[4][4][4];
    #pragma unroll
    for (int mt = 0; mt < 4; mt++)
        #pragma unroll
        for (int nt = 0; nt < 4; nt++)
            #pragma unroll
            for (int i = 0; i < 4; i++) acc[mt][nt][i] = 0.f;

    float4 ra[4], rb[4];
    #pragma unroll
    for (int i = 0; i < 4; i++) {
        ra[i] = *reinterpret_cast<const float4*>(Ap + i*4);
        rb[i] = *reinterpret_cast<const float4*>(Bp + i*4);
    }

    for (int k0 = 0; k0 < DIM; k0 += 32) {
        #pragma unroll
        for (int i = 0; i < 4; i++) {
            uint4 ua = make_uint4(f2tf32(ra[i].x), f2tf32(ra[i].y), f2tf32(ra[i].z), f2tf32(ra[i].w));
            uint4 ub = make_uint4(f2tf32(rb[i].x), f2tf32(rb[i].y), f2tf32(rb[i].z), f2tf32(rb[i].w));
            *reinterpret_cast<uint4*>(&As[ldr][ldc + i*4]) = ua;
            *reinterpret_cast<uint4*>(&Bs[ldr][ldc + i*4]) = ub;
        }
        __syncthreads();
        if (k0 + 32 < DIM) {
            #pragma unroll
            for (int i = 0; i < 4; i++) {
                ra[i] = *reinterpret_cast<const float4*>(Ap + k0 + 32 + i*4);
                rb[i] = *reinterpret_cast<const float4*>(Bp + k0 + 32 + i*4);
            }
        }
        #pragma unroll
        for (int ks = 0; ks < 4; ks++) {
            const int kb = ks * 8;
            uint32_t af[4][4], bf[4][2];
            #pragma unroll
            for (int mt = 0; mt < 4; mt++) {
                const int m = warpM*64 + mt*16 + (lane >> 2);
                af[mt][0] = As[m    ][kb + (lane & 3)];
                af[mt][1] = As[m + 8][kb + (lane & 3)];
                af[mt][2] = As[m    ][kb + (lane & 3) + 4];
                af[mt][3] = As[m + 8][kb + (lane & 3) + 4];
            }
            #pragma unroll
            for (int nt = 0; nt < 4; nt++) {
                const int n = warpN*32 + nt*8 + (lane >> 2);
                bf[nt][0] = Bs[n][kb + (lane & 3)];
                bf[nt][1] = Bs[n][kb + (lane & 3) + 4];
            }
            #pragma unroll
            for (int mt = 0; mt < 4; mt++)
                #pragma unroll
                for (int nt = 0; nt < 4; nt++)
                    mma_tf32(acc[mt][nt], af[mt], bf[nt]);
        }
        __syncthreads();
    }

    #pragma unroll
    for (int nt = 0; nt < 4; nt++) {
        const int c = col0 + warpN*32 + nt*8 + 2*(lane & 3);
        const float b0v = bias[c];
        const float b1v = bias[c + 1];
        #pragma unroll
        for (int mt = 0; mt < 4; mt++) {
            const int r = row0 + warpM*64 + mt*16 + (lane >> 2);
            float2 o0 = make_float2(acc[mt][nt][0] + b0v, acc[mt][nt][1] + b1v);
            float2 o1 = make_float2(acc[mt][nt][2] + b0v, acc[mt][nt][3] + b1v);
            *reinterpret_cast<float2*>(Y + (size_t)r * DIM + c)       = o0;
            *reinterpret_cast<float2*>(Y + (size_t)(r + 8) * DIM + c) = o1;
        }
    }
}

// ============================================================
// TF32 V projection on the 64 reachable tokens per batch.
// Row r -> (b = r>>6, j = r&63), token = 1 + (6+j/8)*14 + (6+j%8)
// ============================================================
__global__ __launch_bounds__(256) void k_gemm_v_t(
    const float* __restrict__ X,
    const float* __restrict__ Wv, const float* __restrict__ bv)
{
    __shared__ __align__(16) uint32_t As[128][36];
    __shared__ __align__(16) uint32_t Bs[128][36];

    const int tid  = threadIdx.x;
    const int lane = tid & 31;
    const int wid  = tid >> 5;
    const int warpM = wid & 1;
    const int warpN = wid >> 1;

    const int row0 = blockIdx.x * 128;
    const int col0 = blockIdx.y * 128;

    const int ldr = tid >> 1;
    const int ldc = (tid & 1) * 16;

    const int r_g = row0 + ldr;
    const int bb  = r_g >> 6;
    const int jj  = r_g & 63;
    const int token = 1 + (6 + (jj >> 3)) * GRID + (6 + (jj & 7));
    const float* Ap = X + (size_t)(bb * SEQ + token) * DIM + ldc;
    const float* Bp = Wv + (size_t)(col0 + ldr) * DIM + ldc;

    float acc[4][4][4];
    #pragma unroll
    for (int mt = 0; mt < 4; mt++)
        #pragma unroll
        for (int nt = 0; nt < 4; nt++)
            #pragma unroll
            for (int i = 0; i < 4; i++) acc[mt][nt][i] = 0.f;

    float4 ra[4], rb[4];
    #pragma unroll
    for (int i = 0; i < 4; i++) {
        ra[i] = *reinterpret_cast<const float4*>(Ap + i*4);
        rb[i] = *reinterpret_cast<const float4*>(Bp + i*4);
    }

    for (int k0 = 0; k0 < DIM; k0 += 32) {
        #pragma unroll
        for (int i = 0; i < 4; i++) {
            uint4 ua = make_uint4(f2tf32(ra[i].x), f2tf32(ra[i].y), f2tf32(ra[i].z), f2tf32(ra[i].w));
            uint4 ub = make_uint4(f2tf32(rb[i].x), f2tf32(rb[i].y), f2tf32(rb[i].z), f2tf32(rb[i].w));
            *reinterpret_cast<uint4*>(&As[ldr][ldc + i*4]) = ua;
            *reinterpret_cast<uint4*>(&Bs[ldr][ldc + i*4]) = ub;
        }
        __syncthreads();
        if (k0 + 32 < DIM) {
            #pragma unroll
            for (int i = 0; i < 4; i++) {
                ra[i] = *reinterpret_cast<const float4*>(Ap + k0 + 32 + i*4);
                rb[i] = *reinterpret_cast<const float4*>(Bp + k0 + 32 + i*4);
            }
        }
        #pragma unroll
        for (int ks = 0; ks < 4; ks++) {
            const int kb = ks * 8;
            uint32_t af[4][4], bf[4][2];
            #pragma unroll
            for (int mt = 0; mt < 4; mt++) {
                const int m = warpM*64 + mt*16 + (lane >> 2);
                af[mt][0] = As[m    ][kb + (lane & 3)];
                af[mt][1] = As[m + 8][kb + (lane & 3)];
                af[mt][2] = As[m    ][kb + (lane & 3) + 4];
                af[mt][3] = As[m + 8][kb + (lane & 3) + 4];
            }
            #pragma unroll
            for (int nt = 0; nt < 4; nt++) {
                const int n = warpN*32 + nt*8 + (lane >> 2);
                bf[nt][0] = Bs[n][kb + (lane & 3)];
                bf[nt][1] = Bs[n][kb + (lane & 3) + 4];
            }
            #pragma unroll
            for (int mt = 0; mt < 4; mt++)
                #pragma unroll
                for (int nt = 0; nt < 4; nt++)
                    mma_tf32(acc[mt][nt], af[mt], bf[nt]);
        }
        __syncthreads();
    }

    #pragma unroll
    for (int nt = 0; nt < 4; nt++) {
        const int c = col0 + warpN*32 + nt*8 + 2*(lane & 3);
        const float b0v = bv[c];
        const float b1v = bv[c + 1];
        #pragma unroll
        for (int mt = 0; mt < 4; mt++) {
            const int r = row0 + warpM*64 + mt*16 + (lane >> 2);
            float2 o0 = make_float2(acc[mt][nt][0] + b0v, acc[mt][nt][1] + b1v);
            float2 o1 = make_float2(acc[mt][nt][2] + b0v, acc[mt][nt][3] + b1v);
            *reinterpret_cast<float2*>(g_vs + (size_t)r * DIM + c)       = o0;
            *reinterpret_cast<float2*>(g_vs + (size_t)(r + 8) * DIM + c) = o1;
        }
    }
}

// ============================================================
// TF32 MLP layer 1: h1 = relu(concat(q_nc,k_nc) @ W1^T + b1)
// M=50176, K=1536, N=60 (tile 64, guarded).
// Block 128x64; 8 warps = 4(M) x 2(N); warp tile 32x32.
// ============================================================
__global__ __launch_bounds__(256) void k_gemm_h1_t(
    const float* __restrict__ W1, const float* __restrict__ b1)
{
    __shared__ __align__(16) uint32_t As[128][36];
    __shared__ __align__(16) uint32_t Bs[64][36];

    const int tid  = threadIdx.x;
    const int lane = tid & 31;
    const int wid  = tid >> 5;
    const int warpM = wid & 3;     // 0..3  (32 rows each)
    const int warpN = wid >> 2;    // 0..1  (32 cols each)

    const int row0 = blockIdx.x * 128;

    const int ldr = tid >> 1;
    const int ldc = (tid & 1) * 16;

    const int r_g = row0 + ldr;
    const int bb  = r_g / SN;
    const int tt  = r_g - bb * SN;
    const size_t aoff = (size_t)(bb * SEQ + tt + 1) * DIM + ldc;

    const int ldr2 = tid >> 2;            // 0..63
    const int ldc2 = (tid & 3) * 8;       // 0,8,16,24
    const bool bvalid = (ldr2 < H60);
    const float* Bp = W1 + (size_t)ldr2 * K2 + ldc2;

    float acc[2][4][4];
    #pragma unroll
    for (int mt = 0; mt < 2; mt++)
        #pragma unroll
        for (int nt = 0; nt < 4; nt++)
            #pragma unroll
            for (int i = 0; i < 4; i++) acc[mt][nt][i] = 0.f;

    float4 ra[4], rb[2];
    {
        const float* base = g_q + aoff;   // k0 = 0 is in q half
        #pragma unroll
        for (int i = 0; i < 4; i++)
            ra[i] = *reinterpret_cast<const float4*>(base + i*4);
        #pragma unroll
        for (int i = 0; i < 2; i++)
            rb[i] = bvalid ? *reinterpret_cast<const float4*>(Bp + i*4)
                           : make_float4(0.f, 0.f, 0.f, 0.f);
    }

    for (int k0 = 0; k0 < K2; k0 += 32) {
        #pragma unroll
        for (int i = 0; i < 4; i++) {
            uint4 ua = make_uint4(f2tf32(ra[i].x), f2tf32(ra[i].y), f2tf32(ra[i].z), f2tf32(ra[i].w));
            *reinterpret_cast<uint4*>(&As[ldr][ldc + i*4]) = ua;
        }
        #pragma unroll
        for (int i = 0; i < 2; i++) {
            uint4 ub = make_uint4(f2tf32(rb[i].x), f2tf32(rb[i].y), f2tf32(rb[i].z), f2tf32(rb[i].w));
            *reinterpret_cast<uint4*>(&Bs[ldr2][ldc2 + i*4]) = ub;
        }
        __syncthreads();
        if (k0 + 32 < K2) {
            const int kn = k0 + 32;
            const float* base = (kn < DIM) ? (g_q + aoff + kn) : (g_k + aoff + kn - DIM);
            #pragma unroll
            for (int i = 0; i < 4; i++)
                ra[i] = *reinterpret_cast<const float4*>(base + i*4);
            #pragma unroll
            for (int i = 0; i < 2; i++)
                rb[i] = bvalid ? *reinterpret_cast<const float4*>(Bp + kn + i*4)
                               : make_float4(0.f, 0.f, 0.f, 0.f);
        }
        #pragma unroll
        for (int ks = 0; ks < 4; ks++) {
            const int kb = ks * 8;
            uint32_t af[2][4], bf[4][2];
            #pragma unroll
            for (int mt = 0; mt < 2; mt++) {
                const int m = warpM*32 + mt*16 + (lane >> 2);
                af[mt][0] = As[m    ][kb + (lane & 3)];
                af[mt][1] = As[m + 8][kb + (lane & 3)];
                af[mt][2] = As[m    ][kb + (lane & 3) + 4];
                af[mt][3] = As[m + 8][kb + (lane & 3) + 4];
            }
            #pragma unroll
            for (int nt = 0; nt < 4; nt++) {
                const int n = warpN*32 + nt*8 + (lane >> 2);
                bf[nt][0] = Bs[n][kb + (lane & 3)];
                bf[nt][1] = Bs[n][kb + (lane & 3) + 4];
            }
            #pragma unroll
            for (int mt = 0; mt < 2; mt++)
                #pragma unroll
                for (int nt = 0; nt < 4; nt++)
                    mma_tf32(acc[mt][nt], af[mt], bf[nt]);
        }
        __syncthreads();
    }

    #pragma unroll
    for (int nt = 0; nt < 4; nt++) {
        const int c = warpN*32 + nt*8 + 2*(lane & 3);
        const float b0v = (c     < H60) ? b1[c]     : 0.f;
        const float b1v = (c + 1 < H60) ? b1[c + 1] : 0.f;
        #pragma unroll
        for (int mt = 0; mt < 2; mt++) {
            const int r = row0 + warpM*32 + mt*16 + (lane >> 2);
            if (c < H60) {
                g_h1[(size_t)r * H60 + c]       = fmaxf(acc[mt][nt][0] + b0v, 0.f);
                g_h1[(size_t)(r + 8) * H60 + c] = fmaxf(acc[mt][nt][2] + b0v, 0.f);
            }
            if (c + 1 < H60) {
                g_h1[(size_t)r * H60 + c + 1]       = fmaxf(acc[mt][nt][1] + b1v, 0.f);
                g_h1[(size_t)(r + 8) * H60 + c + 1] = fmaxf(acc[mt][nt][3] + b1v, 0.f);
            }
        }
    }
}

// ============================================================
// MLP layers 2+3: h2 = relu(h1@W2^T+b2); sample = sigmoid(h2@W3^T+b3)
// 4 tokens per 256-thread block; W2 cached in smem (stride 61: no conflicts).
// ============================================================
__global__ __launch_bounds__(256) void k_mlp23(
    const float* __restrict__ W2, const float* __restrict__ b2,
    const float* __restrict__ W3, const float* __restrict__ b3)
{
    __shared__ float W2s[60 * 61];
    __shared__ float W3s[120];
    __shared__ float b2s[60], b3s[2];
    __shared__ float h1s[4][60];
    __shared__ float h2s[4][60];

    const int tid = threadIdx.x;
    for (int i = tid; i < 3600; i += 256) {
        int rr = i / 60, cc = i - rr * 60;
        W2s[rr * 61 + cc] = W2[i];
    }
    if (tid < 120) W3s[tid] = W3[tid];
    if (tid < 60)  b2s[tid] = b2[tid];
    if (tid < 2)   b3s[tid] = b3[tid];

    const int tl = tid >> 6;      // 0..3 token within block
    const int f  = tid & 63;
    const int r  = blockIdx.x * 4 + tl;
    if (f < H60) h1s[tl][f] = g_h1[(size_t)r * H60 + f];
    __syncthreads();

    if (f < H60) {
        float s = b2s[f];
        #pragma unroll 6
        for (int g = 0; g < H60; g++) s = fmaf(W2s[f*61 + g], h1s[tl][g], s);
        h2s[tl][f] = fmaxf(s, 0.f);
    }
    __syncthreads();

    if (tid < 8) {
        int t2 = tid >> 1, c = tid & 1;
        float s = b3s[c];
        #pragma unroll 6
        for (int g = 0; g < H60; g++) s = fmaf(W3s[c*60 + g], h2s[t2][g], s);
        int rr = blockIdx.x * 4 + t2;
        g_sample[(size_t)rr * 2 + c] = 1.f / (1.f + expf(-s));
    }
}

// ============================================================
// Grid coordinate shuffle + unnormalize.
// ============================================================
__global__ void k_coords()
{
    const int id = blockIdx.x * 256 + threadIdx.x;   // 196*256 = exactly 50176
    const int b = id / SN;
    const int p = id - b * SN;
    const int q1 = 2 * p;
    const int q2 = 2 * p + 1;
    float gx = (q1 < SN) ? g_sample[(size_t)(b*SN + q1)*2 + 0]
                         : g_sample[(size_t)(b*SN + q1 - SN)*2 + 1];
    float gy = (q2 < SN) ? g_sample[(size_t)(b*SN + q2)*2 + 0]
                         : g_sample[(size_t)(b*SN + q2 - SN)*2 + 1];
    g_coords[(size_t)id*2 + 0] = ((gx + 1.f) * (float)GRID - 1.f) * 0.5f;
    g_coords[(size_t)id*2 + 1] = ((gy + 1.f) * (float)GRID - 1.f) * 0.5f;
}

// ============================================================
// Epilogue: per (b,s) block — bilinear gather sk/sv, score = dot(sk,q),
// out = sigmoid(TEMP*score) * sv.  s=0 is the CLS row (sk=sv=1).
// ============================================================
__global__ __launch_bounds__(256) void k_epilogue(float* __restrict__ out)
{
    const int bs = blockIdx.x;              // 0..50431
    const int b  = bs / SEQ;
    const int s  = bs - b * SEQ;
    const int tid = threadIdx.x;
    const int lane = tid & 31;
    const int wid  = tid >> 5;
    __shared__ float red[8];
    __shared__ float sigsh;

    const size_t qbase = (size_t)bs * DIM;

    float  w[4];
    size_t rowk[4], rowv[4];
    bool   vk[4], vv[4];

    if (s > 0) {
        const int p = s - 1;
        const float ix = g_coords[(size_t)(b*SN + p)*2 + 0];
        const float iy = g_coords[(size_t)(b*SN + p)*2 + 1];
        const float ix0f = floorf(ix), iy0f = floorf(iy);
        const float wx1 = ix - ix0f, wx0 = 1.f - wx1;
        const float wy1 = iy - iy0f, wy0 = 1.f - wy1;
        const int x0 = (int)ix0f, y0 = (int)iy0f;
        const int xs[4] = {x0, x0+1, x0,   x0+1};
        const int ys[4] = {y0, y0,   y0+1, y0+1};
        const float ws[4] = {wy0*wx0, wy0*wx1, wy1*wx0, wy1*wx1};
        #pragma unroll
        for (int c = 0; c < 4; c++) {
            const int x = xs[c], y = ys[c];
            const bool v = (x >= 0) && (x <= GRID-1) && (y >= 0) && (y <= GRID-1);
            vk[c] = v;
            w[c]  = ws[c];
            const int tok = 1 + y * GRID + x;
            rowk[c] = v ? (size_t)(b * SEQ + tok) * DIM : 0;
            const bool v2 = v && (x >= 6) && (y >= 6);   // reachable set
            vv[c]   = v2;
            rowv[c] = v2 ? (size_t)(b * 64 + (y-6)*8 + (x-6)) * DIM : 0;
        }
    }

    float part = 0.f;
    float svreg[3];
    #pragma unroll
    for (int it = 0; it < 3; it++) {
        const int d = tid + it * 256;
        float skd, svd;
        if (s == 0) {
            skd = 1.f; svd = 1.f;
        } else {
            skd = 0.f; svd = 0.f;
            #pragma unroll
            for (int c = 0; c < 4; c++) {
                if (vk[c]) skd = fmaf(w[c], g_k[rowk[c] + d], skd);
                if (vv[c]) svd = fmaf(w[c], g_vs[rowv[c] + d], svd);
            }
        }
        svreg[it] = svd;
        part = fmaf(skd, g_q[qbase + d], part);
    }

    #pragma unroll
    for (int off = 16; off > 0; off >>= 1)
        part += __shfl_xor_sync(0xffffffffu, part, off);
    if (lane == 0) red[wid] = part;
    __syncthreads();
    if (tid == 0) {
        float sum = 0.f;
        #pragma unroll
        for (int i = 0; i < 8; i++) sum += red[i];
        sigsh = 1.f / (1.f + expf(-0.01f * sum));
    }
    __syncthreads();
    const float sg = sigsh;
    #pragma unroll
    for (int it = 0; it < 3; it++)
        out[qbase + tid + it * 256] = sg * svreg[it];
}

// ============================================================
extern "C" void kernel_launch(void* const* d_in, const int* in_sizes, int n_in,
                              void* d_out, int out_size)
{
    const float* x   = (const float*)d_in[0];
    // d_in[1] = mask (unused by reference result)
    const float* Wq  = (const float*)d_in[2];
    const float* bq  = (const float*)d_in[3];
    const float* Wk  = (const float*)d_in[4];
    const float* bk  = (const float*)d_in[5];
    const float* Wv  = (const float*)d_in[6];
    const float* bv  = (const float*)d_in[7];
    const float* W1  = (const float*)d_in[8];
    const float* b1  = (const float*)d_in[9];
    const float* W2  = (const float*)d_in[10];
    const float* b2  = (const float*)d_in[11];
    const float* W3  = (const float*)d_in[12];
    const float* b3  = (const float*)d_in[13];
    float* out = (float*)d_out;

    // Q,K full projections: M=50432 (394 tiles), N=768 (6 tiles), z selects Q/K
    k_gemm_qk_t<<<dim3(394, 6, 2), 256>>>(x, Wq, bq, Wk, bk);
    // V projection on the 64 reachable tokens/batch: M=16384 (128 tiles)
    k_gemm_v_t<<<dim3(128, 6), 256>>>(x, Wv, bv);
    // MLP layer 1 (reads g_q, g_k): M=50176 (392 tiles)
    k_gemm_h1_t<<<dim3(392, 1), 256>>>(W1, b1);
    // MLP layers 2+3 -> sample
    k_mlp23<<<12544, 256>>>(W2, b2, W3, b3);
    // grid coordinate shuffle
    k_coords<<<196, 256>>>();
    // bilinear sample + scores + output
    k_epilogue<<<MQK, 256>>>(out);
}

// round 5
// speedup vs baseline: 2.3421x; 1.0333x over previous
#include <cuda_runtime.h>
#include <cstdint>

// Problem dims (fixed by the dataset)
#define BATCH 256
#define SEQ   197
#define SN    196      // SEQ-1
#define DIM   768
#define GRID  14
#define MQK   (BATCH*SEQ)    // 50432
#define MH    (BATCH*SN)     // 50176
#define MV    (BATCH*64)     // 16384 (only 8x8 grid cells [6,13]^2 reachable)
#define H60   60
#define K2    1536

// -------- scratch (__device__ globals; no allocation allowed) --------
__device__ float g_q [(size_t)MQK * DIM];
__device__ float g_k [(size_t)MQK * DIM];
__device__ float g_vs[(size_t)MV  * DIM];
__device__ float g_h1[(size_t)MH  * H60];
__device__ float g_sample[(size_t)MH * 2];
__device__ float g_coords[(size_t)MH * 2];

// ---------------- tf32 / mma helpers ----------------
__device__ __forceinline__ uint32_t f2tf32(float f) {
    uint32_t u;
    asm("cvt.rna.tf32.f32 %0, %1;" : "=r"(u) : "f"(f));
    return u;
}

__device__ __forceinline__ void mma_tf32(float (&d)[4], const uint32_t (&a)[4], const uint32_t (&b)[2]) {
    asm volatile(
        "mma.sync.aligned.m16n8k8.row.col.f32.tf32.tf32.f32 "
        "{%0,%1,%2,%3}, {%4,%5,%6,%7}, {%8,%9}, {%0,%1,%2,%3};\n"
        : "+f"(d[0]), "+f"(d[1]), "+f"(d[2]), "+f"(d[3])
        : "r"(a[0]), "r"(a[1]), "r"(a[2]), "r"(a[3]), "r"(b[0]), "r"(b[1]));
}

// ldmatrix x4: four 8x8 b16 (= 8x4 b32) tiles. Address per lane.
__device__ __forceinline__ void ldsm_x4(uint32_t& r0, uint32_t& r1, uint32_t& r2, uint32_t& r3, uint32_t addr) {
    asm volatile("ldmatrix.sync.aligned.m8n8.x4.shared.b16 {%0,%1,%2,%3}, [%4];"
                 : "=r"(r0), "=r"(r1), "=r"(r2), "=r"(r3) : "r"(addr));
}

// ============================================================
// TF32 tensor-core GEMM: Y[r,e] = sum_d A[r,d]*W[e,d] + bias[e]
// Block 128x128, K-step 32. 8 warps = 2(M) x 4(N); warp tile 64x32.
// Fragment loads via ldmatrix. Q and K share via blockIdx.z.
// ============================================================
__global__ __launch_bounds__(256) void k_gemm_qk_t(
    const float* __restrict__ X,
    const float* __restrict__ Wq, const float* __restrict__ bq,
    const float* __restrict__ Wk, const float* __restrict__ bk)
{
    const float* W    = blockIdx.z ? Wk : Wq;
    const float* bias = blockIdx.z ? bk : bq;
    float*       Y    = blockIdx.z ? g_k : g_q;

    __shared__ __align__(16) uint32_t As[128][36];
    __shared__ __align__(16) uint32_t Bs[128][36];

    const int tid  = threadIdx.x;
    const int lane = tid & 31;
    const int wid  = tid >> 5;
    const int warpM = wid & 1;
    const int warpN = wid >> 1;

    const int row0 = blockIdx.x * 128;
    const int col0 = blockIdx.y * 128;

    const int ldr = tid >> 1;
    const int ldc = (tid & 1) * 16;

    const float* Ap = X + (size_t)(row0 + ldr) * DIM + ldc;
    const float* Bp = W + (size_t)(col0 + ldr) * DIM + ldc;

    // per-lane ldmatrix base addresses (byte, shared space)
    const uint32_t As_addr = (uint32_t)__cvta_generic_to_shared(&As[0][0]);
    const uint32_t Bs_addr = (uint32_t)__cvta_generic_to_shared(&Bs[0][0]);
    const uint32_t a_base = As_addr + (((warpM*64 + (lane & 15)) * 36 + ((lane >> 4) << 2)) << 2);
    const uint32_t b_base = Bs_addr + (((warpN*32 + (lane & 15)) * 36 + ((lane >> 4) << 2)) << 2);

    float acc[4][4][4];
    #pragma unroll
    for (int mt = 0; mt < 4; mt++)
        #pragma unroll
        for (int nt = 0; nt < 4; nt++)
            #pragma unroll
            for (int i = 0; i < 4; i++) acc[mt][nt][i] = 0.f;

    float4 ra[4], rb[4];
    #pragma unroll
    for (int i = 0; i < 4; i++) {
        ra[i] = *reinterpret_cast<const float4*>(Ap + i*4);
        rb[i] = *reinterpret_cast<const float4*>(Bp + i*4);
    }

    for (int k0 = 0; k0 < DIM; k0 += 32) {
        #pragma unroll
        for (int i = 0; i < 4; i++) {
            uint4 ua = make_uint4(f2tf32(ra[i].x), f2tf32(ra[i].y), f2tf32(ra[i].z), f2tf32(ra[i].w));
            uint4 ub = make_uint4(f2tf32(rb[i].x), f2tf32(rb[i].y), f2tf32(rb[i].z), f2tf32(rb[i].w));
            *reinterpret_cast<uint4*>(&As[ldr][ldc + i*4]) = ua;
            *reinterpret_cast<uint4*>(&Bs[ldr][ldc + i*4]) = ub;
        }
        __syncthreads();
        if (k0 + 32 < DIM) {
            #pragma unroll
            for (int i = 0; i < 4; i++) {
                ra[i] = *reinterpret_cast<const float4*>(Ap + k0 + 32 + i*4);
                rb[i] = *reinterpret_cast<const float4*>(Bp + k0 + 32 + i*4);
            }
        }
        #pragma unroll
        for (int ks = 0; ks < 4; ks++) {
            uint32_t af[4][4], bf[4][2];
            #pragma unroll
            for (int mt = 0; mt < 4; mt++)
                ldsm_x4(af[mt][0], af[mt][1], af[mt][2], af[mt][3],
                        a_base + ((mt*16*36 + ks*8) << 2));
            #pragma unroll
            for (int nt2 = 0; nt2 < 2; nt2++) {
                uint32_t r0, r1, r2, r3;
                ldsm_x4(r0, r1, r2, r3, b_base + ((nt2*16*36 + ks*8) << 2));
                bf[2*nt2  ][0] = r0; bf[2*nt2+1][0] = r1;
                bf[2*nt2  ][1] = r2; bf[2*nt2+1][1] = r3;
            }
            #pragma unroll
            for (int mt = 0; mt < 4; mt++)
                #pragma unroll
                for (int nt = 0; nt < 4; nt++)
                    mma_tf32(acc[mt][nt], af[mt], bf[nt]);
        }
        __syncthreads();
    }

    #pragma unroll
    for (int nt = 0; nt < 4; nt++) {
        const int c = col0 + warpN*32 + nt*8 + 2*(lane & 3);
        const float b0v = bias[c];
        const float b1v = bias[c + 1];
        #pragma unroll
        for (int mt = 0; mt < 4; mt++) {
            const int r = row0 + warpM*64 + mt*16 + (lane >> 2);
            float2 o0 = make_float2(acc[mt][nt][0] + b0v, acc[mt][nt][1] + b1v);
            float2 o1 = make_float2(acc[mt][nt][2] + b0v, acc[mt][nt][3] + b1v);
            *reinterpret_cast<float2*>(Y + (size_t)r * DIM + c)       = o0;
            *reinterpret_cast<float2*>(Y + (size_t)(r + 8) * DIM + c) = o1;
        }
    }
}

// ============================================================
// TF32 V projection on the 64 reachable tokens per batch.
// Row r -> (b = r>>6, j = r&63), token = 1 + (6+j/8)*14 + (6+j%8)
// ============================================================
__global__ __launch_bounds__(256) void k_gemm_v_t(
    const float* __restrict__ X,
    const float* __restrict__ Wv, const float* __restrict__ bv)
{
    __shared__ __align__(16) uint32_t As[128][36];
    __shared__ __align__(16) uint32_t Bs[128][36];

    const int tid  = threadIdx.x;
    const int lane = tid & 31;
    const int wid  = tid >> 5;
    const int warpM = wid & 1;
    const int warpN = wid >> 1;

    const int row0 = blockIdx.x * 128;
    const int col0 = blockIdx.y * 128;

    const int ldr = tid >> 1;
    const int ldc = (tid & 1) * 16;

    const int r_g = row0 + ldr;
    const int bb  = r_g >> 6;
    const int jj  = r_g & 63;
    const int token = 1 + (6 + (jj >> 3)) * GRID + (6 + (jj & 7));
    const float* Ap = X + (size_t)(bb * SEQ + token) * DIM + ldc;
    const float* Bp = Wv + (size_t)(col0 + ldr) * DIM + ldc;

    const uint32_t As_addr = (uint32_t)__cvta_generic_to_shared(&As[0][0]);
    const uint32_t Bs_addr = (uint32_t)__cvta_generic_to_shared(&Bs[0][0]);
    const uint32_t a_base = As_addr + (((warpM*64 + (lane & 15)) * 36 + ((lane >> 4) << 2)) << 2);
    const uint32_t b_base = Bs_addr + (((warpN*32 + (lane & 15)) * 36 + ((lane >> 4) << 2)) << 2);

    float acc[4][4][4];
    #pragma unroll
    for (int mt = 0; mt < 4; mt++)
        #pragma unroll
        for (int nt = 0; nt < 4; nt++)
            #pragma unroll
            for (int i = 0; i < 4; i++) acc[mt][nt][i] = 0.f;

    float4 ra[4], rb[4];
    #pragma unroll
    for (int i = 0; i < 4; i++) {
        ra[i] = *reinterpret_cast<const float4*>(Ap + i*4);
        rb[i] = *reinterpret_cast<const float4*>(Bp + i*4);
    }

    for (int k0 = 0; k0 < DIM; k0 += 32) {
        #pragma unroll
        for (int i = 0; i < 4; i++) {
            uint4 ua = make_uint4(f2tf32(ra[i].x), f2tf32(ra[i].y), f2tf32(ra[i].z), f2tf32(ra[i].w));
            uint4 ub = make_uint4(f2tf32(rb[i].x), f2tf32(rb[i].y), f2tf32(rb[i].z), f2tf32(rb[i].w));
            *reinterpret_cast<uint4*>(&As[ldr][ldc + i*4]) = ua;
            *reinterpret_cast<uint4*>(&Bs[ldr][ldc + i*4]) = ub;
        }
        __syncthreads();
        if (k0 + 32 < DIM) {
            #pragma unroll
            for (int i = 0; i < 4; i++) {
                ra[i] = *reinterpret_cast<const float4*>(Ap + k0 + 32 + i*4);
                rb[i] = *reinterpret_cast<const float4*>(Bp + k0 + 32 + i*4);
            }
        }
        #pragma unroll
        for (int ks = 0; ks < 4; ks++) {
            uint32_t af[4][4], bf[4][2];
            #pragma unroll
            for (int mt = 0; mt < 4; mt++)
                ldsm_x4(af[mt][0], af[mt][1], af[mt][2], af[mt][3],
                        a_base + ((mt*16*36 + ks*8) << 2));
            #pragma unroll
            for (int nt2 = 0; nt2 < 2; nt2++) {
                uint32_t r0, r1, r2, r3;
                ldsm_x4(r0, r1, r2, r3, b_base + ((nt2*16*36 + ks*8) << 2));
                bf[2*nt2  ][0] = r0; bf[2*nt2+1][0] = r1;
                bf[2*nt2  ][1] = r2; bf[2*nt2+1][1] = r3;
            }
            #pragma unroll
            for (int mt = 0; mt < 4; mt++)
                #pragma unroll
                for (int nt = 0; nt < 4; nt++)
                    mma_tf32(acc[mt][nt], af[mt], bf[nt]);
        }
        __syncthreads();
    }

    #pragma unroll
    for (int nt = 0; nt < 4; nt++) {
        const int c = col0 + warpN*32 + nt*8 + 2*(lane & 3);
        const float b0v = bv[c];
        const float b1v = bv[c + 1];
        #pragma unroll
        for (int mt = 0; mt < 4; mt++) {
            const int r = row0 + warpM*64 + mt*16 + (lane >> 2);
            float2 o0 = make_float2(acc[mt][nt][0] + b0v, acc[mt][nt][1] + b1v);
            float2 o1 = make_float2(acc[mt][nt][2] + b0v, acc[mt][nt][3] + b1v);
            *reinterpret_cast<float2*>(g_vs + (size_t)r * DIM + c)       = o0;
            *reinterpret_cast<float2*>(g_vs + (size_t)(r + 8) * DIM + c) = o1;
        }
    }
}

// ============================================================
// TF32 MLP layer 1: h1 = relu(concat(q_nc,k_nc) @ W1^T + b1)
// M=50176, K=1536, N=60 (tile 64, guarded).
// Block 128x64; 8 warps = 4(M) x 2(N); warp tile 32x32.
// ============================================================
__global__ __launch_bounds__(256) void k_gemm_h1_t(
    const float* __restrict__ W1, const float* __restrict__ b1)
{
    __shared__ __align__(16) uint32_t As[128][36];
    __shared__ __align__(16) uint32_t Bs[64][36];

    const int tid  = threadIdx.x;
    const int lane = tid & 31;
    const int wid  = tid >> 5;
    const int warpM = wid & 3;     // 0..3  (32 rows each)
    const int warpN = wid >> 2;    // 0..1  (32 cols each)

    const int row0 = blockIdx.x * 128;

    const int ldr = tid >> 1;
    const int ldc = (tid & 1) * 16;

    const int r_g = row0 + ldr;
    const int bb  = r_g / SN;
    const int tt  = r_g - bb * SN;
    const size_t aoff = (size_t)(bb * SEQ + tt + 1) * DIM + ldc;

    const int ldr2 = tid >> 2;            // 0..63
    const int ldc2 = (tid & 3) * 8;       // 0,8,16,24
    const bool bvalid = (ldr2 < H60);
    const float* Bp = W1 + (size_t)ldr2 * K2 + ldc2;

    const uint32_t As_addr = (uint32_t)__cvta_generic_to_shared(&As[0][0]);
    const uint32_t Bs_addr = (uint32_t)__cvta_generic_to_shared(&Bs[0][0]);
    const uint32_t a_base = As_addr + (((warpM*32 + (lane & 15)) * 36 + ((lane >> 4) << 2)) << 2);
    const uint32_t b_base = Bs_addr + (((warpN*32 + (lane & 15)) * 36 + ((lane >> 4) << 2)) << 2);

    float acc[2][4][4];
    #pragma unroll
    for (int mt = 0; mt < 2; mt++)
        #pragma unroll
        for (int nt = 0; nt < 4; nt++)
            #pragma unroll
            for (int i = 0; i < 4; i++) acc[mt][nt][i] = 0.f;

    float4 ra[4], rb[2];
    {
        const float* base = g_q + aoff;   // k0 = 0 is in q half
        #pragma unroll
        for (int i = 0; i < 4; i++)
            ra[i] = *reinterpret_cast<const float4*>(base + i*4);
        #pragma unroll
        for (int i = 0; i < 2; i++)
            rb[i] = bvalid ? *reinterpret_cast<const float4*>(Bp + i*4)
                           : make_float4(0.f, 0.f, 0.f, 0.f);
    }

    for (int k0 = 0; k0 < K2; k0 += 32) {
        #pragma unroll
        for (int i = 0; i < 4; i++) {
            uint4 ua = make_uint4(f2tf32(ra[i].x), f2tf32(ra[i].y), f2tf32(ra[i].z), f2tf32(ra[i].w));
            *reinterpret_cast<uint4*>(&As[ldr][ldc + i*4]) = ua;
        }
        #pragma unroll
        for (int i = 0; i < 2; i++) {
            uint4 ub = make_uint4(f2tf32(rb[i].x), f2tf32(rb[i].y), f2tf32(rb[i].z), f2tf32(rb[i].w));
            *reinterpret_cast<uint4*>(&Bs[ldr2][ldc2 + i*4]) = ub;
        }
        __syncthreads();
        if (k0 + 32 < K2) {
            const int kn = k0 + 32;
            const float* base = (kn < DIM) ? (g_q + aoff + kn) : (g_k + aoff + kn - DIM);
            #pragma unroll
            for (int i = 0; i < 4; i++)
                ra[i] = *reinterpret_cast<const float4*>(base + i*4);
            #pragma unroll
            for (int i = 0; i < 2; i++)
                rb[i] = bvalid ? *reinterpret_cast<const float4*>(Bp + kn + i*4)
                               : make_float4(0.f, 0.f, 0.f, 0.f);
        }
        #pragma unroll
        for (int ks = 0; ks < 4; ks++) {
            uint32_t af[2][4], bf[4][2];
            #pragma unroll
            for (int mt = 0; mt < 2; mt++)
                ldsm_x4(af[mt][0], af[mt][1], af[mt][2], af[mt][3],
                        a_base + ((mt*16*36 + ks*8) << 2));
            #pragma unroll
            for (int nt2 = 0; nt2 < 2; nt2++) {
                uint32_t r0, r1, r2, r3;
                ldsm_x4(r0, r1, r2, r3, b_base + ((nt2*16*36 + ks*8) << 2));
                bf[2*nt2  ][0] = r0; bf[2*nt2+1][0] = r1;
                bf[2*nt2  ][1] = r2; bf[2*nt2+1][1] = r3;
            }
            #pragma unroll
            for (int mt = 0; mt < 2; mt++)
                #pragma unroll
                for (int nt = 0; nt < 4; nt++)
                    mma_tf32(acc[mt][nt], af[mt], bf[nt]);
        }
        __syncthreads();
    }

    #pragma unroll
    for (int nt = 0; nt < 4; nt++) {
        const int c = warpN*32 + nt*8 + 2*(lane & 3);
        const float b0v = (c     < H60) ? b1[c]     : 0.f;
        const float b1v = (c + 1 < H60) ? b1[c + 1] : 0.f;
        #pragma unroll
        for (int mt = 0; mt < 2; mt++) {
            const int r = row0 + warpM*32 + mt*16 + (lane >> 2);
            if (c < H60) {
                g_h1[(size_t)r * H60 + c]       = fmaxf(acc[mt][nt][0] + b0v, 0.f);
                g_h1[(size_t)(r + 8) * H60 + c] = fmaxf(acc[mt][nt][2] + b0v, 0.f);
            }
            if (c + 1 < H60) {
                g_h1[(size_t)r * H60 + c + 1]       = fmaxf(acc[mt][nt][1] + b1v, 0.f);
                g_h1[(size_t)(r + 8) * H60 + c + 1] = fmaxf(acc[mt][nt][3] + b1v, 0.f);
            }
        }
    }
}

// ============================================================
// MLP layers 2+3: h2 = relu(h1@W2^T+b2); sample = sigmoid(h2@W3^T+b3)
// 16 tokens per 256-thread block (W2 DRAM reload amortized 4x more);
// each thread handles 4 tokens -> 4 FMA per W2s LDS.
// ============================================================
__global__ __launch_bounds__(256) void k_mlp23(
    const float* __restrict__ W2, const float* __restrict__ b2,
    const float* __restrict__ W3, const float* __restrict__ b3)
{
    __shared__ float W2s[60 * 61];
    __shared__ float W3s[120];
    __shared__ float b2s[60], b3s[2];
    __shared__ float h1s[16][60];
    __shared__ float h2s[16][60];

    const int tid = threadIdx.x;
    for (int i = tid; i < 3600; i += 256) {
        int rr = i / 60, cc = i - rr * 60;
        W2s[rr * 61 + cc] = W2[i];
    }
    if (tid < 120) W3s[tid] = W3[tid];
    if (tid < 60)  b2s[tid] = b2[tid];
    if (tid < 2)   b3s[tid] = b3[tid];

    const int r0 = blockIdx.x * 16;
    for (int i = tid; i < 16 * 60; i += 256) {
        int t = i / 60, c = i - t * 60;
        h1s[t][c] = g_h1[(size_t)(r0 + t) * H60 + c];
    }
    __syncthreads();

    const int tg = tid >> 6;      // 0..3 -> tokens tg*4 .. tg*4+3
    const int f  = tid & 63;
    if (f < H60) {
        float a0 = b2s[f], a1 = b2s[f], a2 = b2s[f], a3 = b2s[f];
        #pragma unroll 4
        for (int g = 0; g < H60; g++) {
            const float w = W2s[f*61 + g];
            a0 = fmaf(w, h1s[tg*4 + 0][g], a0);
            a1 = fmaf(w, h1s[tg*4 + 1][g], a1);
            a2 = fmaf(w, h1s[tg*4 + 2][g], a2);
            a3 = fmaf(w, h1s[tg*4 + 3][g], a3);
        }
        h2s[tg*4 + 0][f] = fmaxf(a0, 0.f);
        h2s[tg*4 + 1][f] = fmaxf(a1, 0.f);
        h2s[tg*4 + 2][f] = fmaxf(a2, 0.f);
        h2s[tg*4 + 3][f] = fmaxf(a3, 0.f);
    }
    __syncthreads();

    if (tid < 32) {
        int t2 = tid >> 1, c = tid & 1;
        float s = b3s[c];
        #pragma unroll 4
        for (int g = 0; g < H60; g++) s = fmaf(W3s[c*60 + g], h2s[t2][g], s);
        g_sample[(size_t)(r0 + t2) * 2 + c] = 1.f / (1.f + expf(-s));
    }
}

// ============================================================
// Grid coordinate shuffle + unnormalize.
// ============================================================
__global__ void k_coords()
{
    const int id = blockIdx.x * 256 + threadIdx.x;   // 196*256 = exactly 50176
    const int b = id / SN;
    const int p = id - b * SN;
    const int q1 = 2 * p;
    const int q2 = 2 * p + 1;
    float gx = (q1 < SN) ? g_sample[(size_t)(b*SN + q1)*2 + 0]
                         : g_sample[(size_t)(b*SN + q1 - SN)*2 + 1];
    float gy = (q2 < SN) ? g_sample[(size_t)(b*SN + q2)*2 + 0]
                         : g_sample[(size_t)(b*SN + q2 - SN)*2 + 1];
    g_coords[(size_t)id*2 + 0] = ((gx + 1.f) * (float)GRID - 1.f) * 0.5f;
    g_coords[(size_t)id*2 + 1] = ((gy + 1.f) * (float)GRID - 1.f) * 0.5f;
}

// ============================================================
// Epilogue: per (b,s) block — bilinear gather sk/sv, score = dot(sk,q),
// out = sigmoid(TEMP*score) * sv.  s=0 is the CLS row (sk=sv=1).
// ============================================================
__global__ __launch_bounds__(256) void k_epilogue(float* __restrict__ out)
{
    const int bs = blockIdx.x;              // 0..50431
    const int b  = bs / SEQ;
    const int s  = bs - b * SEQ;
    const int tid = threadIdx.x;
    const int lane = tid & 31;
    const int wid  = tid >> 5;
    __shared__ float red[8];
    __shared__ float sigsh;

    const size_t qbase = (size_t)bs * DIM;

    float  w[4];
    size_t rowk[4], rowv[4];
    bool   vk[4], vv[4];

    if (s > 0) {
        const int p = s - 1;
        const float ix = g_coords[(size_t)(b*SN + p)*2 + 0];
        const float iy = g_coords[(size_t)(b*SN + p)*2 + 1];
        const float ix0f = floorf(ix), iy0f = floorf(iy);
        const float wx1 = ix - ix0f, wx0 = 1.f - wx1;
        const float wy1 = iy - iy0f, wy0 = 1.f - wy1;
        const int x0 = (int)ix0f, y0 = (int)iy0f;
        const int xs[4] = {x0, x0+1, x0,   x0+1};
        const int ys[4] = {y0, y0,   y0+1, y0+1};
        const float ws[4] = {wy0*wx0, wy0*wx1, wy1*wx0, wy1*wx1};
        #pragma unroll
        for (int c = 0; c < 4; c++) {
            const int x = xs[c], y = ys[c];
            const bool v = (x >= 0) && (x <= GRID-1) && (y >= 0) && (y <= GRID-1);
            vk[c] = v;
            w[c]  = ws[c];
            const int tok = 1 + y * GRID + x;
            rowk[c] = v ? (size_t)(b * SEQ + tok) * DIM : 0;
            const bool v2 = v && (x >= 6) && (y >= 6);   // reachable set
            vv[c]   = v2;
            rowv[c] = v2 ? (size_t)(b * 64 + (y-6)*8 + (x-6)) * DIM : 0;
        }
    }

    float part = 0.f;
    float svreg[3];
    #pragma unroll
    for (int it = 0; it < 3; it++) {
        const int d = tid + it * 256;
        float skd, svd;
        if (s == 0) {
            skd = 1.f; svd = 1.f;
        } else {
            skd = 0.f; svd = 0.f;
            #pragma unroll
            for (int c = 0; c < 4; c++) {
                if (vk[c]) skd = fmaf(w[c], g_k[rowk[c] + d], skd);
                if (vv[c]) svd = fmaf(w[c], g_vs[rowv[c] + d], svd);
            }
        }
        svreg[it] = svd;
        part = fmaf(skd, g_q[qbase + d], part);
    }

    #pragma unroll
    for (int off = 16; off > 0; off >>= 1)
        part += __shfl_xor_sync(0xffffffffu, part, off);
    if (lane == 0) red[wid] = part;
    __syncthreads();
    if (tid == 0) {
        float sum = 0.f;
        #pragma unroll
        for (int i = 0; i < 8; i++) sum += red[i];
        sigsh = 1.f / (1.f + expf(-0.01f * sum));
    }
    __syncthreads();
    const float sg = sigsh;
    #pragma unroll
    for (int it = 0; it < 3; it++)
        out[qbase + tid + it * 256] = sg * svreg[it];
}

// ============================================================
extern "C" void kernel_launch(void* const* d_in, const int* in_sizes, int n_in,
                              void* d_out, int out_size)
{
    const float* x   = (const float*)d_in[0];
    // d_in[1] = mask (unused by reference result)
    const float* Wq  = (const float*)d_in[2];
    const float* bq  = (const float*)d_in[3];
    const float* Wk  = (const float*)d_in[4];
    const float* bk  = (const float*)d_in[5];
    const float* Wv  = (const float*)d_in[6];
    const float* bv  = (const float*)d_in[7];
    const float* W1  = (const float*)d_in[8];
    const float* b1  = (const float*)d_in[9];
    const float* W2  = (const float*)d_in[10];
    const float* b2  = (const float*)d_in[11];
    const float* W3  = (const float*)d_in[12];
    const float* b3  = (const float*)d_in[13];
    float* out = (float*)d_out;

    // Q,K full projections: M=50432 (394 tiles), N=768 (6 tiles), z selects Q/K
    k_gemm_qk_t<<<dim3(394, 6, 2), 256>>>(x, Wq, bq, Wk, bk);
    // V projection on the 64 reachable tokens/batch: M=16384 (128 tiles)
    k_gemm_v_t<<<dim3(128, 6), 256>>>(x, Wv, bv);
    // MLP layer 1 (reads g_q, g_k): M=50176 (392 tiles)
    k_gemm_h1_t<<<dim3(392, 1), 256>>>(W1, b1);
    // MLP layers 2+3 -> sample (16 tokens per block)
    k_mlp23<<<3136, 256>>>(W2, b2, W3, b3);
    // grid coordinate shuffle
    k_coords<<<196, 256>>>();
    // bilinear sample + scores + output
    k_epilogue<<<MQK, 256>>>(out);
}

// round 6
// speedup vs baseline: 2.5001x; 1.0675x over previous
#include <cuda_runtime.h>
#include <cstdint>

// Problem dims (fixed by the dataset)
#define BATCH 256
#define SEQ   197
#define SN    196      // SEQ-1
#define DIM   768
#define GRID  14
#define MQK   (BATCH*SEQ)    // 50432
#define MH    (BATCH*SN)     // 50176
#define MV    (BATCH*64)     // 16384 (only 8x8 grid cells [6,13]^2 reachable)
#define H60   60
#define K2    1536

// -------- scratch (__device__ globals; no allocation allowed) --------
__device__ float g_q [(size_t)MQK * DIM];
__device__ float g_k [(size_t)MQK * DIM];
__device__ float g_vs[(size_t)MV  * DIM];
__device__ float g_h1[(size_t)MH  * H60];
__device__ float g_sample[(size_t)MH * 2];
__device__ float g_coords[(size_t)MH * 2];

// ---------------- tf32 / mma helpers ----------------
__device__ __forceinline__ uint32_t f2tf32(float f) {
    uint32_t u;
    asm("cvt.rna.tf32.f32 %0, %1;" : "=r"(u) : "f"(f));
    return u;
}

__device__ __forceinline__ void mma_tf32(float (&d)[4], const uint32_t (&a)[4], const uint32_t (&b)[2]) {
    asm volatile(
        "mma.sync.aligned.m16n8k8.row.col.f32.tf32.tf32.f32 "
        "{%0,%1,%2,%3}, {%4,%5,%6,%7}, {%8,%9}, {%0,%1,%2,%3};\n"
        : "+f"(d[0]), "+f"(d[1]), "+f"(d[2]), "+f"(d[3])
        : "r"(a[0]), "r"(a[1]), "r"(a[2]), "r"(a[3]), "r"(b[0]), "r"(b[1]));
}

// ldmatrix x4: four 8x8 b16 (= 8x4 b32) tiles. Address per lane.
__device__ __forceinline__ void ldsm_x4(uint32_t& r0, uint32_t& r1, uint32_t& r2, uint32_t& r3, uint32_t addr) {
    asm volatile("ldmatrix.sync.aligned.m8n8.x4.shared.b16 {%0,%1,%2,%3}, [%4];"
                 : "=r"(r0), "=r"(r1), "=r"(r2), "=r"(r3) : "r"(addr));
}

// ============================================================
// TF32 tensor-core GEMM: Y[r,e] = sum_d A[r,d]*W[e,d] + bias[e]
// Block 128x128, K-step 32. 8 warps = 2(M) x 4(N); warp tile 64x32.
// 1-D grid: blockIdx.x = rowTile*12 + (z*6 + colTile)  -- col/z fastest,
// so the 12 blocks sharing one X row tile run in the same wave (L2 reuse).
// ============================================================
__global__ __launch_bounds__(256) void k_gemm_qk_t(
    const float* __restrict__ X,
    const float* __restrict__ Wq, const float* __restrict__ bq,
    const float* __restrict__ Wk, const float* __restrict__ bk)
{
    const int bx  = blockIdx.x;
    const int rt  = bx / 12;           // row tile 0..393
    const int rem = bx - rt * 12;      // 0..11 (fastest)
    const int ct  = rem % 6;           // column tile
    const int zz  = rem / 6;           // 0=Q, 1=K

    const float* W    = zz ? Wk : Wq;
    const float* bias = zz ? bk : bq;
    float*       Y    = zz ? g_k : g_q;

    __shared__ __align__(16) uint32_t As[128][36];
    __shared__ __align__(16) uint32_t Bs[128][36];

    const int tid  = threadIdx.x;
    const int lane = tid & 31;
    const int wid  = tid >> 5;
    const int warpM = wid & 1;
    const int warpN = wid >> 1;

    const int row0 = rt * 128;
    const int col0 = ct * 128;

    const int ldr = tid >> 1;
    const int ldc = (tid & 1) * 16;

    const float* Ap = X + (size_t)(row0 + ldr) * DIM + ldc;
    const float* Bp = W + (size_t)(col0 + ldr) * DIM + ldc;

    // per-lane ldmatrix base addresses (byte, shared space)
    const uint32_t As_addr = (uint32_t)__cvta_generic_to_shared(&As[0][0]);
    const uint32_t Bs_addr = (uint32_t)__cvta_generic_to_shared(&Bs[0][0]);
    const uint32_t a_base = As_addr + (((warpM*64 + (lane & 15)) * 36 + ((lane >> 4) << 2)) << 2);
    const uint32_t b_base = Bs_addr + (((warpN*32 + (lane & 15)) * 36 + ((lane >> 4) << 2)) << 2);

    float acc[4][4][4];
    #pragma unroll
    for (int mt = 0; mt < 4; mt++)
        #pragma unroll
        for (int nt = 0; nt < 4; nt++)
            #pragma unroll
            for (int i = 0; i < 4; i++) acc[mt][nt][i] = 0.f;

    float4 ra[4], rb[4];
    #pragma unroll
    for (int i = 0; i < 4; i++) {
        ra[i] = *reinterpret_cast<const float4*>(Ap + i*4);
        rb[i] = *reinterpret_cast<const float4*>(Bp + i*4);
    }

    for (int k0 = 0; k0 < DIM; k0 += 32) {
        #pragma unroll
        for (int i = 0; i < 4; i++) {
            uint4 ua = make_uint4(f2tf32(ra[i].x), f2tf32(ra[i].y), f2tf32(ra[i].z), f2tf32(ra[i].w));
            uint4 ub = make_uint4(f2tf32(rb[i].x), f2tf32(rb[i].y), f2tf32(rb[i].z), f2tf32(rb[i].w));
            *reinterpret_cast<uint4*>(&As[ldr][ldc + i*4]) = ua;
            *reinterpret_cast<uint4*>(&Bs[ldr][ldc + i*4]) = ub;
        }
        __syncthreads();
        if (k0 + 32 < DIM) {
            #pragma unroll
            for (int i = 0; i < 4; i++) {
                ra[i] = *reinterpret_cast<const float4*>(Ap + k0 + 32 + i*4);
                rb[i] = *reinterpret_cast<const float4*>(Bp + k0 + 32 + i*4);
            }
        }
        #pragma unroll
        for (int ks = 0; ks < 4; ks++) {
            uint32_t af[4][4], bf[4][2];
            #pragma unroll
            for (int mt = 0; mt < 4; mt++)
                ldsm_x4(af[mt][0], af[mt][1], af[mt][2], af[mt][3],
                        a_base + ((mt*16*36 + ks*8) << 2));
            #pragma unroll
            for (int nt2 = 0; nt2 < 2; nt2++) {
                uint32_t r0, r1, r2, r3;
                ldsm_x4(r0, r1, r2, r3, b_base + ((nt2*16*36 + ks*8) << 2));
                bf[2*nt2  ][0] = r0; bf[2*nt2+1][0] = r1;
                bf[2*nt2  ][1] = r2; bf[2*nt2+1][1] = r3;
            }
            #pragma unroll
            for (int mt = 0; mt < 4; mt++)
                #pragma unroll
                for (int nt = 0; nt < 4; nt++)
                    mma_tf32(acc[mt][nt], af[mt], bf[nt]);
        }
        __syncthreads();
    }

    #pragma unroll
    for (int nt = 0; nt < 4; nt++) {
        const int c = col0 + warpN*32 + nt*8 + 2*(lane & 3);
        const float b0v = bias[c];
        const float b1v = bias[c + 1];
        #pragma unroll
        for (int mt = 0; mt < 4; mt++) {
            const int r = row0 + warpM*64 + mt*16 + (lane >> 2);
            float2 o0 = make_float2(acc[mt][nt][0] + b0v, acc[mt][nt][1] + b1v);
            float2 o1 = make_float2(acc[mt][nt][2] + b0v, acc[mt][nt][3] + b1v);
            *reinterpret_cast<float2*>(Y + (size_t)r * DIM + c)       = o0;
            *reinterpret_cast<float2*>(Y + (size_t)(r + 8) * DIM + c) = o1;
        }
    }
}

// ============================================================
// TF32 V projection on the 64 reachable tokens per batch.
// Row r -> (b = r>>6, j = r&63), token = 1 + (6+j/8)*14 + (6+j%8)
// 1-D grid: blockIdx.x = rowTile*6 + colTile (col fastest for L2 reuse).
// ============================================================
__global__ __launch_bounds__(256) void k_gemm_v_t(
    const float* __restrict__ X,
    const float* __restrict__ Wv, const float* __restrict__ bv)
{
    __shared__ __align__(16) uint32_t As[128][36];
    __shared__ __align__(16) uint32_t Bs[128][36];

    const int bx = blockIdx.x;
    const int rt = bx / 6;
    const int ct = bx - rt * 6;

    const int tid  = threadIdx.x;
    const int lane = tid & 31;
    const int wid  = tid >> 5;
    const int warpM = wid & 1;
    const int warpN = wid >> 1;

    const int row0 = rt * 128;
    const int col0 = ct * 128;

    const int ldr = tid >> 1;
    const int ldc = (tid & 1) * 16;

    const int r_g = row0 + ldr;
    const int bb  = r_g >> 6;
    const int jj  = r_g & 63;
    const int token = 1 + (6 + (jj >> 3)) * GRID + (6 + (jj & 7));
    const float* Ap = X + (size_t)(bb * SEQ + token) * DIM + ldc;
    const float* Bp = Wv + (size_t)(col0 + ldr) * DIM + ldc;

    const uint32_t As_addr = (uint32_t)__cvta_generic_to_shared(&As[0][0]);
    const uint32_t Bs_addr = (uint32_t)__cvta_generic_to_shared(&Bs[0][0]);
    const uint32_t a_base = As_addr + (((warpM*64 + (lane & 15)) * 36 + ((lane >> 4) << 2)) << 2);
    const uint32_t b_base = Bs_addr + (((warpN*32 + (lane & 15)) * 36 + ((lane >> 4) << 2)) << 2);

    float acc[4][4][4];
    #pragma unroll
    for (int mt = 0; mt < 4; mt++)
        #pragma unroll
        for (int nt = 0; nt < 4; nt++)
            #pragma unroll
            for (int i = 0; i < 4; i++) acc[mt][nt][i] = 0.f;

    float4 ra[4], rb[4];
    #pragma unroll
    for (int i = 0; i < 4; i++) {
        ra[i] = *reinterpret_cast<const float4*>(Ap + i*4);
        rb[i] = *reinterpret_cast<const float4*>(Bp + i*4);
    }

    for (int k0 = 0; k0 < DIM; k0 += 32) {
        #pragma unroll
        for (int i = 0; i < 4; i++) {
            uint4 ua = make_uint4(f2tf32(ra[i].x), f2tf32(ra[i].y), f2tf32(ra[i].z), f2tf32(ra[i].w));
            uint4 ub = make_uint4(f2tf32(rb[i].x), f2tf32(rb[i].y), f2tf32(rb[i].z), f2tf32(rb[i].w));
            *reinterpret_cast<uint4*>(&As[ldr][ldc + i*4]) = ua;
            *reinterpret_cast<uint4*>(&Bs[ldr][ldc + i*4]) = ub;
        }
        __syncthreads();
        if (k0 + 32 < DIM) {
            #pragma unroll
            for (int i = 0; i < 4; i++) {
                ra[i] = *reinterpret_cast<const float4*>(Ap + k0 + 32 + i*4);
                rb[i] = *reinterpret_cast<const float4*>(Bp + k0 + 32 + i*4);
            }
        }
        #pragma unroll
        for (int ks = 0; ks < 4; ks++) {
            uint32_t af[4][4], bf[4][2];
            #pragma unroll
            for (int mt = 0; mt < 4; mt++)
                ldsm_x4(af[mt][0], af[mt][1], af[mt][2], af[mt][3],
                        a_base + ((mt*16*36 + ks*8) << 2));
            #pragma unroll
            for (int nt2 = 0; nt2 < 2; nt2++) {
                uint32_t r0, r1, r2, r3;
                ldsm_x4(r0, r1, r2, r3, b_base + ((nt2*16*36 + ks*8) << 2));
                bf[2*nt2  ][0] = r0; bf[2*nt2+1][0] = r1;
                bf[2*nt2  ][1] = r2; bf[2*nt2+1][1] = r3;
            }
            #pragma unroll
            for (int mt = 0; mt < 4; mt++)
                #pragma unroll
                for (int nt = 0; nt < 4; nt++)
                    mma_tf32(acc[mt][nt], af[mt], bf[nt]);
        }
        __syncthreads();
    }

    #pragma unroll
    for (int nt = 0; nt < 4; nt++) {
        const int c = col0 + warpN*32 + nt*8 + 2*(lane & 3);
        const float b0v = bv[c];
        const float b1v = bv[c + 1];
        #pragma unroll
        for (int mt = 0; mt < 4; mt++) {
            const int r = row0 + warpM*64 + mt*16 + (lane >> 2);
            float2 o0 = make_float2(acc[mt][nt][0] + b0v, acc[mt][nt][1] + b1v);
            float2 o1 = make_float2(acc[mt][nt][2] + b0v, acc[mt][nt][3] + b1v);
            *reinterpret_cast<float2*>(g_vs + (size_t)r * DIM + c)       = o0;
            *reinterpret_cast<float2*>(g_vs + (size_t)(r + 8) * DIM + c) = o1;
        }
    }
}

// ============================================================
// TF32 MLP layer 1: h1 = relu(concat(q_nc,k_nc) @ W1^T + b1)
// M=50176, K=1536, N=60 (tile 64, guarded).
// Block 128x64; 8 warps = 4(M) x 2(N); warp tile 32x32.
// ============================================================
__global__ __launch_bounds__(256) void k_gemm_h1_t(
    const float* __restrict__ W1, const float* __restrict__ b1)
{
    __shared__ __align__(16) uint32_t As[128][36];
    __shared__ __align__(16) uint32_t Bs[64][36];

    const int tid  = threadIdx.x;
    const int lane = tid & 31;
    const int wid  = tid >> 5;
    const int warpM = wid & 3;     // 0..3  (32 rows each)
    const int warpN = wid >> 2;    // 0..1  (32 cols each)

    const int row0 = blockIdx.x * 128;

    const int ldr = tid >> 1;
    const int ldc = (tid & 1) * 16;

    const int r_g = row0 + ldr;
    const int bb  = r_g / SN;
    const int tt  = r_g - bb * SN;
    const size_t aoff = (size_t)(bb * SEQ + tt + 1) * DIM + ldc;

    const int ldr2 = tid >> 2;            // 0..63
    const int ldc2 = (tid & 3) * 8;       // 0,8,16,24
    const bool bvalid = (ldr2 < H60);
    const float* Bp = W1 + (size_t)ldr2 * K2 + ldc2;

    const uint32_t As_addr = (uint32_t)__cvta_generic_to_shared(&As[0][0]);
    const uint32_t Bs_addr = (uint32_t)__cvta_generic_to_shared(&Bs[0][0]);
    const uint32_t a_base = As_addr + (((warpM*32 + (lane & 15)) * 36 + ((lane >> 4) << 2)) << 2);
    const uint32_t b_base = Bs_addr + (((warpN*32 + (lane & 15)) * 36 + ((lane >> 4) << 2)) << 2);

    float acc[2][4][4];
    #pragma unroll
    for (int mt = 0; mt < 2; mt++)
        #pragma unroll
        for (int nt = 0; nt < 4; nt++)
            #pragma unroll
            for (int i = 0; i < 4; i++) acc[mt][nt][i] = 0.f;

    float4 ra[4], rb[2];
    {
        const float* base = g_q + aoff;   // k0 = 0 is in q half
        #pragma unroll
        for (int i = 0; i < 4; i++)
            ra[i] = *reinterpret_cast<const float4*>(base + i*4);
        #pragma unroll
        for (int i = 0; i < 2; i++)
            rb[i] = bvalid ? *reinterpret_cast<const float4*>(Bp + i*4)
                           : make_float4(0.f, 0.f, 0.f, 0.f);
    }

    for (int k0 = 0; k0 < K2; k0 += 32) {
        #pragma unroll
        for (int i = 0; i < 4; i++) {
            uint4 ua = make_uint4(f2tf32(ra[i].x), f2tf32(ra[i].y), f2tf32(ra[i].z), f2tf32(ra[i].w));
            *reinterpret_cast<uint4*>(&As[ldr][ldc + i*4]) = ua;
        }
        #pragma unroll
        for (int i = 0; i < 2; i++) {
            uint4 ub = make_uint4(f2tf32(rb[i].x), f2tf32(rb[i].y), f2tf32(rb[i].z), f2tf32(rb[i].w));
            *reinterpret_cast<uint4*>(&Bs[ldr2][ldc2 + i*4]) = ub;
        }
        __syncthreads();
        if (k0 + 32 < K2) {
            const int kn = k0 + 32;
            const float* base = (kn < DIM) ? (g_q + aoff + kn) : (g_k + aoff + kn - DIM);
            #pragma unroll
            for (int i = 0; i < 4; i++)
                ra[i] = *reinterpret_cast<const float4*>(base + i*4);
            #pragma unroll
            for (int i = 0; i < 2; i++)
                rb[i] = bvalid ? *reinterpret_cast<const float4*>(Bp + kn + i*4)
                               : make_float4(0.f, 0.f, 0.f, 0.f);
        }
        #pragma unroll
        for (int ks = 0; ks < 4; ks++) {
            uint32_t af[2][4], bf[4][2];
            #pragma unroll
            for (int mt = 0; mt < 2; mt++)
                ldsm_x4(af[mt][0], af[mt][1], af[mt][2], af[mt][3],
                        a_base + ((mt*16*36 + ks*8) << 2));
            #pragma unroll
            for (int nt2 = 0; nt2 < 2; nt2++) {
                uint32_t r0, r1, r2, r3;
                ldsm_x4(r0, r1, r2, r3, b_base + ((nt2*16*36 + ks*8) << 2));
                bf[2*nt2  ][0] = r0; bf[2*nt2+1][0] = r1;
                bf[2*nt2  ][1] = r2; bf[2*nt2+1][1] = r3;
            }
            #pragma unroll
            for (int mt = 0; mt < 2; mt++)
                #pragma unroll
                for (int nt = 0; nt < 4; nt++)
                    mma_tf32(acc[mt][nt], af[mt], bf[nt]);
        }
        __syncthreads();
    }

    #pragma unroll
    for (int nt = 0; nt < 4; nt++) {
        const int c = warpN*32 + nt*8 + 2*(lane & 3);
        const float b0v = (c     < H60) ? b1[c]     : 0.f;
        const float b1v = (c + 1 < H60) ? b1[c + 1] : 0.f;
        #pragma unroll
        for (int mt = 0; mt < 2; mt++) {
            const int r = row0 + warpM*32 + mt*16 + (lane >> 2);
            if (c < H60) {
                g_h1[(size_t)r * H60 + c]       = fmaxf(acc[mt][nt][0] + b0v, 0.f);
                g_h1[(size_t)(r + 8) * H60 + c] = fmaxf(acc[mt][nt][2] + b0v, 0.f);
            }
            if (c + 1 < H60) {
                g_h1[(size_t)r * H60 + c + 1]       = fmaxf(acc[mt][nt][1] + b1v, 0.f);
                g_h1[(size_t)(r + 8) * H60 + c + 1] = fmaxf(acc[mt][nt][3] + b1v, 0.f);
            }
        }
    }
}

// ============================================================
// MLP layers 2+3: h2 = relu(h1@W2^T+b2); sample = sigmoid(h2@W3^T+b3)
// 16 tokens per 256-thread block; each thread-group does 4 tokens.
// ============================================================
__global__ __launch_bounds__(256) void k_mlp23(
    const float* __restrict__ W2, const float* __restrict__ b2,
    const float* __restrict__ W3, const float* __restrict__ b3)
{
    __shared__ float W2s[60 * 61];
    __shared__ float W3s[120];
    __shared__ float b2s[60], b3s[2];
    __shared__ float h1s[16][60];
    __shared__ float h2s[16][60];

    const int tid = threadIdx.x;
    for (int i = tid; i < 3600; i += 256) {
        int rr = i / 60, cc = i - rr * 60;
        W2s[rr * 61 + cc] = W2[i];
    }
    if (tid < 120) W3s[tid] = W3[tid];
    if (tid < 60)  b2s[tid] = b2[tid];
    if (tid < 2)   b3s[tid] = b3[tid];

    const int r0 = blockIdx.x * 16;
    for (int i = tid; i < 16 * 60; i += 256) {
        int t = i / 60, c = i - t * 60;
        h1s[t][c] = g_h1[(size_t)(r0 + t) * H60 + c];
    }
    __syncthreads();

    const int tg = tid >> 6;      // 0..3 -> tokens tg*4 .. tg*4+3
    const int f  = tid & 63;
    if (f < H60) {
        float a0 = b2s[f], a1 = b2s[f], a2 = b2s[f], a3 = b2s[f];
        #pragma unroll 4
        for (int g = 0; g < H60; g++) {
            const float w = W2s[f*61 + g];
            a0 = fmaf(w, h1s[tg*4 + 0][g], a0);
            a1 = fmaf(w, h1s[tg*4 + 1][g], a1);
            a2 = fmaf(w, h1s[tg*4 + 2][g], a2);
            a3 = fmaf(w, h1s[tg*4 + 3][g], a3);
        }
        h2s[tg*4 + 0][f] = fmaxf(a0, 0.f);
        h2s[tg*4 + 1][f] = fmaxf(a1, 0.f);
        h2s[tg*4 + 2][f] = fmaxf(a2, 0.f);
        h2s[tg*4 + 3][f] = fmaxf(a3, 0.f);
    }
    __syncthreads();

    if (tid < 32) {
        int t2 = tid >> 1, c = tid & 1;
        float s = b3s[c];
        #pragma unroll 4
        for (int g = 0; g < H60; g++) s = fmaf(W3s[c*60 + g], h2s[t2][g], s);
        g_sample[(size_t)(r0 + t2) * 2 + c] = 1.f / (1.f + expf(-s));
    }
}

// ============================================================
// Grid coordinate shuffle + unnormalize.
// ============================================================
__global__ void k_coords()
{
    const int id = blockIdx.x * 256 + threadIdx.x;   // 196*256 = exactly 50176
    const int b = id / SN;
    const int p = id - b * SN;
    const int q1 = 2 * p;
    const int q2 = 2 * p + 1;
    float gx = (q1 < SN) ? g_sample[(size_t)(b*SN + q1)*2 + 0]
                         : g_sample[(size_t)(b*SN + q1 - SN)*2 + 1];
    float gy = (q2 < SN) ? g_sample[(size_t)(b*SN + q2)*2 + 0]
                         : g_sample[(size_t)(b*SN + q2 - SN)*2 + 1];
    g_coords[(size_t)id*2 + 0] = ((gx + 1.f) * (float)GRID - 1.f) * 0.5f;
    g_coords[(size_t)id*2 + 1] = ((gy + 1.f) * (float)GRID - 1.f) * 0.5f;
}

// ============================================================
// Epilogue: per (b,s) block — bilinear gather sk/sv, score = dot(sk,q),
// out = sigmoid(TEMP*score) * sv.  s=0 is the CLS row (sk=sv=1).
// ============================================================
__global__ __launch_bounds__(256) void k_epilogue(float* __restrict__ out)
{
    const int bs = blockIdx.x;              // 0..50431
    const int b  = bs / SEQ;
    const int s  = bs - b * SEQ;
    const int tid = threadIdx.x;
    const int lane = tid & 31;
    const int wid  = tid >> 5;
    __shared__ float red[8];
    __shared__ float sigsh;

    const size_t qbase = (size_t)bs * DIM;

    float  w[4];
    size_t rowk[4], rowv[4];
    bool   vk[4], vv[4];

    if (s > 0) {
        const int p = s - 1;
        const float ix = g_coords[(size_t)(b*SN + p)*2 + 0];
        const float iy = g_coords[(size_t)(b*SN + p)*2 + 1];
        const float ix0f = floorf(ix), iy0f = floorf(iy);
        const float wx1 = ix - ix0f, wx0 = 1.f - wx1;
        const float wy1 = iy - iy0f, wy0 = 1.f - wy1;
        const int x0 = (int)ix0f, y0 = (int)iy0f;
        const int xs[4] = {x0, x0+1, x0,   x0+1};
        const int ys[4] = {y0, y0,   y0+1, y0+1};
        const float ws[4] = {wy0*wx0, wy0*wx1, wy1*wx0, wy1*wx1};
        #pragma unroll
        for (int c = 0; c < 4; c++) {
            const int x = xs[c], y = ys[c];
            const bool v = (x >= 0) && (x <= GRID-1) && (y >= 0) && (y <= GRID-1);
            vk[c] = v;
            w[c]  = ws[c];
            const int tok = 1 + y * GRID + x;
            rowk[c] = v ? (size_t)(b * SEQ + tok) * DIM : 0;
            const bool v2 = v && (x >= 6) && (y >= 6);   // reachable set
            vv[c]   = v2;
            rowv[c] = v2 ? (size_t)(b * 64 + (y-6)*8 + (x-6)) * DIM : 0;
        }
    }

    float part = 0.f;
    float svreg[3];
    #pragma unroll
    for (int it = 0; it < 3; it++) {
        const int d = tid + it * 256;
        float skd, svd;
        if (s == 0) {
            skd = 1.f; svd = 1.f;
        } else {
            skd = 0.f; svd = 0.f;
            #pragma unroll
            for (int c = 0; c < 4; c++) {
                if (vk[c]) skd = fmaf(w[c], g_k[rowk[c] + d], skd);
                if (vv[c]) svd = fmaf(w[c], g_vs[rowv[c] + d], svd);
            }
        }
        svreg[it] = svd;
        part = fmaf(skd, g_q[qbase + d], part);
    }

    #pragma unroll
    for (int off = 16; off > 0; off >>= 1)
        part += __shfl_xor_sync(0xffffffffu, part, off);
    if (lane == 0) red[wid] = part;
    __syncthreads();
    if (tid == 0) {
        float sum = 0.f;
        #pragma unroll
        for (int i = 0; i < 8; i++) sum += red[i];
        sigsh = 1.f / (1.f + expf(-0.01f * sum));
    }
    __syncthreads();
    const float sg = sigsh;
    #pragma unroll
    for (int it = 0; it < 3; it++)
        out[qbase + tid + it * 256] = sg * svreg[it];
}

// ============================================================
extern "C" void kernel_launch(void* const* d_in, const int* in_sizes, int n_in,
                              void* d_out, int out_size)
{
    const float* x   = (const float*)d_in[0];
    // d_in[1] = mask (unused by reference result)
    const float* Wq  = (const float*)d_in[2];
    const float* bq  = (const float*)d_in[3];
    const float* Wk  = (const float*)d_in[4];
    const float* bk  = (const float*)d_in[5];
    const float* Wv  = (const float*)d_in[6];
    const float* bv  = (const float*)d_in[7];
    const float* W1  = (const float*)d_in[8];
    const float* b1  = (const float*)d_in[9];
    const float* W2  = (const float*)d_in[10];
    const float* b2  = (const float*)d_in[11];
    const float* W3  = (const float*)d_in[12];
    const float* b3  = (const float*)d_in[13];
    float* out = (float*)d_out;

    // Q,K full projections: 394 row tiles x (6 col x 2 z), col/z fastest
    k_gemm_qk_t<<<394 * 12, 256>>>(x, Wq, bq, Wk, bk);
    // V projection on the 64 reachable tokens/batch: 128 row tiles x 6 col
    k_gemm_v_t<<<128 * 6, 256>>>(x, Wv, bv);
    // MLP layer 1 (reads g_q, g_k): M=50176 (392 tiles)
    k_gemm_h1_t<<<392, 256>>>(W1, b1);
    // MLP layers 2+3 -> sample (16 tokens per block)
    k_mlp23<<<3136, 256>>>(W2, b2, W3, b3);
    // grid coordinate shuffle
    k_coords<<<196, 256>>>();
    // bilinear sample + scores + output
    k_epilogue<<<MQK, 256>>>(out);
}